// round 2
// baseline (speedup 1.0000x reference)
#include <cuda_runtime.h>
#include <math.h>

// ---------------- problem constants (fixed by setup_inputs) ----------------
#define D_MODEL   1536
#define N_HEADS_C 24
#define DH        64
#define B_SZ      4
#define L_SEQ     2048
#define M_ROWS    (B_SZ * L_SEQ)     // 8192
#define QKV_COLS  (3 * D_MODEL)      // 4608

// ---------------- scratch (no allocations allowed; use device globals) ----
__device__ float g_qkv[(size_t)M_ROWS * QKV_COLS];   // [B*L, 3*D]  (3,H,Dh) column order
__device__ float g_att[(size_t)M_ROWS * D_MODEL];    // [B*L, D] attention output

// ===========================================================================
// SGEMM (NT): C[M,N] = A[M,K] * B[N,K]^T.  BM=BN=128, BK=16, 256 thr, 8x8/thr
// ===========================================================================
__global__ __launch_bounds__(256) void sgemm_nt(
    const float* __restrict__ A, const float* __restrict__ B,
    float* __restrict__ C, int M, int N, int K)
{
    __shared__ float As[16][128];
    __shared__ float Bs[16][128];

    const int t  = threadIdx.x;
    const int tx = t & 15;        // n direction
    const int ty = t >> 4;        // m direction

    const float* Ab = A + (size_t)blockIdx.y * 128 * K;
    const float* Bb = B + (size_t)blockIdx.x * 128 * K;

    float acc[8][8];
#pragma unroll
    for (int i = 0; i < 8; i++)
#pragma unroll
        for (int j = 0; j < 8; j++) acc[i][j] = 0.f;

    for (int k0 = 0; k0 < K; k0 += 16) {
#pragma unroll
        for (int i = 0; i < 2; i++) {
            int idx = t + i * 256;        // 0..511 float4 slots (128 rows x 4)
            int row = idx >> 2;
            int c4  = (idx & 3) << 2;
            float4 av = *(const float4*)(Ab + (size_t)row * K + k0 + c4);
            As[c4 + 0][row] = av.x; As[c4 + 1][row] = av.y;
            As[c4 + 2][row] = av.z; As[c4 + 3][row] = av.w;
            float4 bv = *(const float4*)(Bb + (size_t)row * K + k0 + c4);
            Bs[c4 + 0][row] = bv.x; Bs[c4 + 1][row] = bv.y;
            Bs[c4 + 2][row] = bv.z; Bs[c4 + 3][row] = bv.w;
        }
        __syncthreads();

#pragma unroll
        for (int k = 0; k < 16; k++) {
            float ar[8], br[8];
            *(float4*)&ar[0] = *(const float4*)&As[k][ty * 8];
            *(float4*)&ar[4] = *(const float4*)&As[k][ty * 8 + 4];
            *(float4*)&br[0] = *(const float4*)&Bs[k][tx * 8];
            *(float4*)&br[4] = *(const float4*)&Bs[k][tx * 8 + 4];
#pragma unroll
            for (int i = 0; i < 8; i++)
#pragma unroll
                for (int j = 0; j < 8; j++)
                    acc[i][j] += ar[i] * br[j];
        }
        __syncthreads();
    }

#pragma unroll
    for (int i = 0; i < 8; i++) {
        float* cp = C + (size_t)(blockIdx.y * 128 + ty * 8 + i) * N
                      + blockIdx.x * 128 + tx * 8;
        *(float4*)(cp + 0) = make_float4(acc[i][0], acc[i][1], acc[i][2], acc[i][3]);
        *(float4*)(cp + 4) = make_float4(acc[i][4], acc[i][5], acc[i][6], acc[i][7]);
    }
}

// ===========================================================================
// RoPE in-place on q and k halves of g_qkv. One thread per (bl, which, h, d<32)
// ===========================================================================
__global__ void rope_kernel(float* __restrict__ qkv, const int* __restrict__ pos_offset)
{
    int idx = blockIdx.x * blockDim.x + threadIdx.x;
    int d  = idx & 31;
    int h  = (idx >> 5) % N_HEADS_C;
    int w  = (idx / (32 * N_HEADS_C)) & 1;          // 0 = q, 1 = k
    int bl = idx / (32 * N_HEADS_C * 2);            // 0..8191
    int l  = bl & (L_SEQ - 1);

    float tpos = (float)(l + *pos_offset);
    // inv_freq computed accurately (matches reference's fp32 inv_freq to ~1 ulp)
    float inv  = (float)exp2(-(double)d * (13.287712379549449 / 32.0));
    float fr   = tpos * inv;                         // fp32 product, like reference

    // Cody-Waite range reduction to [-pi, pi] so fast-math sincos stays accurate
    float n  = rintf(fr * 0.15915494309189535f);     // fr / (2*pi)
    float r1 = fmaf(n, -6.2831855f, fr);             // - n * 2pi_hi
    float r  = fmaf(n,  1.7484556e-7f, r1);          // - n * 2pi_lo (2pi = hi - 1.7484556e-7)

    float s, c;
    __sincosf(r, &s, &c);                            // NOTE: sin first, cos second

    float* base = qkv + (size_t)bl * QKV_COLS + w * D_MODEL + h * DH;
    float x1 = base[d];
    float x2 = base[d + 32];
    base[d]      = x1 * c - x2 * s;
    base[d + 32] = x2 * c + x1 * s;
}

// ===========================================================================
// Flash attention (causal). Grid: (L/128, B*H). 128 threads, thread-per-q-row.
// k/v tiles of 64 rows in smem; two-pass online softmax using a smem score buf.
// ===========================================================================
#define ATT_BM 128
#define ATT_BN 64
#define ATT_SMEM ((ATT_BN * DH + ATT_BN * DH + ATT_BN * ATT_BM) * 4)  // 64 KB

__global__ __launch_bounds__(128) void attn_kernel(
    const float* __restrict__ qkv, float* __restrict__ outp)
{
    extern __shared__ float smem[];
    float (*kbuf)[DH]     = (float(*)[DH])smem;                       // 64x64
    float (*vbuf)[DH]     = (float(*)[DH])(smem + ATT_BN * DH);       // 64x64
    float (*sbuf)[ATT_BM] = (float(*)[ATT_BM])(smem + 2 * ATT_BN * DH); // 64x128

    const int qt = blockIdx.x;
    const int bh = blockIdx.y;
    const int b  = bh / N_HEADS_C;
    const int h  = bh % N_HEADS_C;
    const int r  = threadIdx.x;              // q row within tile

    const float* qbase = qkv + (size_t)b * L_SEQ * QKV_COLS + h * DH;
    const float* kbase = qbase + D_MODEL;
    const float* vbase = qbase + 2 * D_MODEL;

    // ---- stage q tile (128x64) through kbuf in two 64-row chunks -> regs ----
    float q[DH];
#pragma unroll
    for (int c = 0; c < 2; c++) {
        const float* gsrc = qbase + (size_t)(qt * ATT_BM + c * 64) * QKV_COLS;
#pragma unroll
        for (int i = 0; i < 8; i++) {
            int idx = i * 128 + r;           // 1024 float4 per 64x64 tile
            int row = idx >> 4;
            int c4  = (idx & 15) << 2;
            *(float4*)&kbuf[row][c4] = *(const float4*)(gsrc + (size_t)row * QKV_COLS + c4);
        }
        __syncthreads();
        if ((r >> 6) == c) {
            int rr = r & 63;
#pragma unroll
            for (int d = 0; d < DH; d++) q[d] = kbuf[rr][d] * 0.125f;  // fold 1/sqrt(64)
        }
        __syncthreads();
    }

    float m = -INFINITY, lsum = 0.f;
    float o[DH];
#pragma unroll
    for (int d = 0; d < DH; d++) o[d] = 0.f;

    const int qrow = qt * ATT_BM + r;
    const int ktmax = 2 * qt + 1;

    for (int kt = 0; kt <= ktmax; kt++) {
        const float* kg = kbase + (size_t)(kt * ATT_BN) * QKV_COLS;
        const float* vg = vbase + (size_t)(kt * ATT_BN) * QKV_COLS;
#pragma unroll
        for (int i = 0; i < 8; i++) {
            int idx = i * 128 + r;
            int row = idx >> 4;
            int c4  = (idx & 15) << 2;
            *(float4*)&kbuf[row][c4] = *(const float4*)(kg + (size_t)row * QKV_COLS + c4);
            *(float4*)&vbuf[row][c4] = *(const float4*)(vg + (size_t)row * QKV_COLS + c4);
        }
        __syncthreads();

        const int jlim = qrow - kt * ATT_BN;     // valid j <= jlim
        float smax = -INFINITY;

        // pass 1: scores for this thread's row
        for (int j = 0; j < ATT_BN; j++) {
            const float4* kr = (const float4*)kbuf[j];
            float s0 = 0.f, s1 = 0.f, s2 = 0.f, s3 = 0.f;
#pragma unroll
            for (int d4 = 0; d4 < 16; d4 += 4) {
                float4 kv0 = kr[d4 + 0];
                s0 += q[4*d4 + 0]*kv0.x + q[4*d4 + 1]*kv0.y + q[4*d4 + 2]*kv0.z + q[4*d4 + 3]*kv0.w;
                float4 kv1 = kr[d4 + 1];
                s1 += q[4*d4 + 4]*kv1.x + q[4*d4 + 5]*kv1.y + q[4*d4 + 6]*kv1.z + q[4*d4 + 7]*kv1.w;
                float4 kv2 = kr[d4 + 2];
                s2 += q[4*d4 + 8]*kv2.x + q[4*d4 + 9]*kv2.y + q[4*d4 +10]*kv2.z + q[4*d4 +11]*kv2.w;
                float4 kv3 = kr[d4 + 3];
                s3 += q[4*d4 +12]*kv3.x + q[4*d4 +13]*kv3.y + q[4*d4 +14]*kv3.z + q[4*d4 +15]*kv3.w;
            }
            float s = (s0 + s1) + (s2 + s3);
            s = (j <= jlim) ? s : -INFINITY;
            sbuf[j][r] = s;
            smax = fmaxf(smax, s);
        }

        // pass 2: online softmax update + o accumulation
        float mnew = fmaxf(m, smax);
        float corr = __expf(m - mnew);          // 0 on first tile (m = -inf)
        lsum *= corr;
#pragma unroll
        for (int d = 0; d < DH; d++) o[d] *= corr;

        for (int j = 0; j < ATT_BN; j++) {
            float p = __expf(sbuf[j][r] - mnew); // 0 for masked entries
            lsum += p;
            const float4* vr = (const float4*)vbuf[j];
#pragma unroll
            for (int d4 = 0; d4 < 16; d4++) {
                float4 vv = vr[d4];
                o[4*d4 + 0] += p * vv.x;
                o[4*d4 + 1] += p * vv.y;
                o[4*d4 + 2] += p * vv.z;
                o[4*d4 + 3] += p * vv.w;
            }
        }
        m = mnew;
        __syncthreads();
    }

    float inv = 1.f / lsum;
    float* op = outp + (size_t)(b * L_SEQ + qrow) * D_MODEL + h * DH;
#pragma unroll
    for (int d4 = 0; d4 < 16; d4++) {
        *(float4*)(op + 4 * d4) = make_float4(o[4*d4 + 0] * inv, o[4*d4 + 1] * inv,
                                              o[4*d4 + 2] * inv, o[4*d4 + 3] * inv);
    }
}

// ===========================================================================
// launch
// ===========================================================================
extern "C" void kernel_launch(void* const* d_in, const int* in_sizes, int n_in,
                              void* d_out, int out_size)
{
    const float* x     = (const float*)d_in[0];
    const float* w_qkv = (const float*)d_in[1];
    const float* w_out = (const float*)d_in[2];
    const int*   pos   = (const int*)d_in[3];
    float*       out   = (float*)d_out;

    float *qkvp = nullptr, *attp = nullptr;
    cudaGetSymbolAddress((void**)&qkvp, g_qkv);
    cudaGetSymbolAddress((void**)&attp, g_att);

    cudaFuncSetAttribute(attn_kernel, cudaFuncAttributeMaxDynamicSharedMemorySize, ATT_SMEM);

    // 1) QKV projection: [8192,1536] x [4608,1536]^T -> [8192,4608]
    sgemm_nt<<<dim3(QKV_COLS / 128, M_ROWS / 128), 256>>>(
        x, w_qkv, qkvp, M_ROWS, QKV_COLS, D_MODEL);

    // 2) RoPE on q and k (in place)
    int rope_total = M_ROWS * 2 * N_HEADS_C * 32;
    rope_kernel<<<rope_total / 256, 256>>>(qkvp, pos);

    // 3) causal flash attention -> g_att [8192,1536]
    attn_kernel<<<dim3(L_SEQ / ATT_BM, B_SZ * N_HEADS_C), 128, ATT_SMEM>>>(qkvp, attp);

    // 4) output projection: [8192,1536] x [1536,1536]^T -> d_out
    sgemm_nt<<<dim3(D_MODEL / 128, M_ROWS / 128), 256>>>(
        attp, w_out, out, M_ROWS, D_MODEL, D_MODEL);
}

// round 5
// speedup vs baseline: 2.5691x; 2.5691x over previous
#include <cuda_runtime.h>
#include <cuda_bf16.h>
#include <math.h>
#include <stdint.h>

// ---------------- problem constants ----------------
#define D_MODEL   1536
#define N_HEADS_C 24
#define DH        64
#define B_SZ      4
#define L_SEQ     2048
#define M_ROWS    (B_SZ * L_SEQ)     // 8192
#define QKV_COLS  (3 * D_MODEL)      // 4608
#define K_DIM     1536

// single dynamic smem symbol shared by all kernels
extern __shared__ char dyn_smem[];

// ---------------- scratch (device globals; no allocation allowed) ---------
__device__ float g_qkv[(size_t)M_ROWS * QKV_COLS];
__device__ float g_att[(size_t)M_ROWS * D_MODEL];
__device__ __nv_bfloat16 g_xh[(size_t)M_ROWS * K_DIM];
__device__ __nv_bfloat16 g_xl[(size_t)M_ROWS * K_DIM];
__device__ __nv_bfloat16 g_wqh[(size_t)QKV_COLS * K_DIM];
__device__ __nv_bfloat16 g_wql[(size_t)QKV_COLS * K_DIM];
__device__ __nv_bfloat16 g_ah[(size_t)M_ROWS * K_DIM];
__device__ __nv_bfloat16 g_al[(size_t)M_ROWS * K_DIM];
__device__ __nv_bfloat16 g_woh[(size_t)D_MODEL * K_DIM];
__device__ __nv_bfloat16 g_wol[(size_t)D_MODEL * K_DIM];

// ---------------- helpers --------------------------------------------------
__device__ __forceinline__ uint32_t smem_u32(const void* p) {
    uint32_t a;
    asm("{ .reg .u64 t; cvta.to.shared.u64 t, %1; cvt.u32.u64 %0, t; }" : "=r"(a) : "l"(p));
    return a;
}

#define CP_ASYNC16(dst, src) \
    asm volatile("cp.async.cg.shared.global [%0], [%1], 16;" :: "r"(dst), "l"(src))
#define CP_COMMIT() asm volatile("cp.async.commit_group;" ::: "memory")
#define CP_WAIT(N)  asm volatile("cp.async.wait_group %0;" :: "n"(N) : "memory")

#define LDSM_X4(r0, r1, r2, r3, addr) \
    asm volatile("ldmatrix.sync.aligned.m8n8.x4.shared.b16 {%0,%1,%2,%3}, [%4];" \
        : "=r"(r0), "=r"(r1), "=r"(r2), "=r"(r3) : "r"(addr))

#define MMA_BF16(c, a, b0_, b1_) \
    asm volatile("mma.sync.aligned.m16n8k16.row.col.f32.bf16.bf16.f32 " \
        "{%0,%1,%2,%3}, {%4,%5,%6,%7}, {%8,%9}, {%0,%1,%2,%3};" \
        : "+f"((c)[0]), "+f"((c)[1]), "+f"((c)[2]), "+f"((c)[3]) \
        : "r"((a)[0]), "r"((a)[1]), "r"((a)[2]), "r"((a)[3]), "r"(b0_), "r"(b1_))

__device__ __forceinline__ uint32_t sw128(uint32_t off) {
    return off ^ ((off >> 3) & 0x70);
}

// ===========================================================================
// split fp32 -> bf16 hi + bf16 lo
// ===========================================================================
__global__ __launch_bounds__(256) void split_bf16(
    const float* __restrict__ s, __nv_bfloat16* __restrict__ hi,
    __nv_bfloat16* __restrict__ lo, int n4)
{
    int i = blockIdx.x * blockDim.x + threadIdx.x;
    if (i >= n4) return;
    float4 v = ((const float4*)s)[i];
    __nv_bfloat16 h0 = __float2bfloat16_rn(v.x);
    __nv_bfloat16 h1 = __float2bfloat16_rn(v.y);
    __nv_bfloat16 h2 = __float2bfloat16_rn(v.z);
    __nv_bfloat16 h3 = __float2bfloat16_rn(v.w);
    __nv_bfloat16 l0 = __float2bfloat16_rn(v.x - __bfloat162float(h0));
    __nv_bfloat16 l1 = __float2bfloat16_rn(v.y - __bfloat162float(h1));
    __nv_bfloat16 l2 = __float2bfloat16_rn(v.z - __bfloat162float(h2));
    __nv_bfloat16 l3 = __float2bfloat16_rn(v.w - __bfloat162float(h3));
    ((ushort4*)hi)[i] = make_ushort4(__bfloat16_as_ushort(h0), __bfloat16_as_ushort(h1),
                                     __bfloat16_as_ushort(h2), __bfloat16_as_ushort(h3));
    ((ushort4*)lo)[i] = make_ushort4(__bfloat16_as_ushort(l0), __bfloat16_as_ushort(l1),
                                     __bfloat16_as_ushort(l2), __bfloat16_as_ushort(l3));
}

// ===========================================================================
// Split-bf16 3-product GEMM via mma.sync (HMMA):
//   C[M,N] = (Ah+Al)[M,K] * (Bh+Bl)[N,K]^T   (Al*Bl dropped)
// BM=BN=128, BK=64 bf16 (128B rows, XOR swizzle), 2-stage cp.async pipeline.
// 8 warps: warp grid 2(M) x 4(N), warp tile 64x32.
// ===========================================================================
#define GK_CHUNKS 24
#define TILE_B    16384                       // 128 rows x 128 bytes
#define STAGE_B   (4 * TILE_B)                // Ah, Al, Bh, Bl
#define GEMM_SMEM (2 * STAGE_B)               // 131072

__global__ __launch_bounds__(256, 1) void gemm_bf16x3(
    const __nv_bfloat16* __restrict__ Ah, const __nv_bfloat16* __restrict__ Al,
    const __nv_bfloat16* __restrict__ Bh, const __nv_bfloat16* __restrict__ Bl,
    float* __restrict__ C, int N)
{
    const uint32_t sbu = smem_u32(dyn_smem);

    const int tid  = threadIdx.x;
    const int wid  = tid >> 5;
    const int lane = tid & 31;
    const int wm   = wid & 1;                 // 0..1  (M, 64 rows)
    const int wn   = wid >> 1;                // 0..3  (N, 32 cols)
    const int m0   = blockIdx.y * 128;
    const int n0   = blockIdx.x * 128;

    const __nv_bfloat16* srcs[4] = {
        Ah + (size_t)m0 * K_DIM, Al + (size_t)m0 * K_DIM,
        Bh + (size_t)n0 * K_DIM, Bl + (size_t)n0 * K_DIM };

    // per-thread load slots: 4 chunks of 16B per operand tile
    int unit_row[4], unit_u[4];
#pragma unroll
    for (int i = 0; i < 4; i++) {
        int unit = tid + i * 256;             // 0..1023
        unit_row[i] = unit >> 3;
        unit_u[i]   = unit & 7;
    }

    auto load_stage = [&](int c, int s) {
        uint32_t sb = sbu + s * STAGE_B;
#pragma unroll
        for (int op = 0; op < 4; op++) {
            const __nv_bfloat16* src = srcs[op] + c * 64;
            uint32_t ob = sb + op * TILE_B;
#pragma unroll
            for (int i = 0; i < 4; i++) {
                const __nv_bfloat16* g = src + (size_t)unit_row[i] * K_DIM + unit_u[i] * 8;
                uint32_t d = ob + sw128(unit_row[i] * 128 + unit_u[i] * 16);
                CP_ASYNC16(d, g);
            }
        }
        CP_COMMIT();
    };

    float acc[4][4][4];                        // [mi][nj][4]
#pragma unroll
    for (int i = 0; i < 4; i++)
#pragma unroll
        for (int j = 0; j < 4; j++)
#pragma unroll
            for (int k = 0; k < 4; k++) acc[i][j][k] = 0.f;

    load_stage(0, 0);
    load_stage(1, 1);

    // ldmatrix lane addressing (same formula for A and B tiles):
    // addr = base + swizzle(row16 * 128 + k16*32 + (lane/16)*16), row16 = lane%16
    const int lrow = lane & 15;
    const int lhalf = (lane >> 4) * 16;

    for (int c = 0; c < GK_CHUNKS; c++) {
        if (c + 2 < GK_CHUNKS) { CP_WAIT(1); } else { CP_WAIT(0); }
        __syncthreads();

        const uint32_t sb = sbu + (c & 1) * STAGE_B;
        const uint32_t aH = sb + 0 * TILE_B;
        const uint32_t aL = sb + 1 * TILE_B;
        const uint32_t bH = sb + 2 * TILE_B;
        const uint32_t bL = sb + 3 * TILE_B;

#pragma unroll
        for (int k16 = 0; k16 < 4; k16++) {
            const uint32_t kb = k16 * 32 + lhalf;
            uint32_t ah[4][4], al[4][4];
#pragma unroll
            for (int i = 0; i < 4; i++) {
                int row = wm * 64 + i * 16 + lrow;
                uint32_t o = sw128(row * 128 + kb);
                LDSM_X4(ah[i][0], ah[i][1], ah[i][2], ah[i][3], aH + o);
                LDSM_X4(al[i][0], al[i][1], al[i][2], al[i][3], aL + o);
            }
            uint32_t bh[2][4], bl[2][4];
#pragma unroll
            for (int j = 0; j < 2; j++) {
                int row = wn * 32 + j * 16 + lrow;
                uint32_t o = sw128(row * 128 + kb);
                LDSM_X4(bh[j][0], bh[j][1], bh[j][2], bh[j][3], bH + o);
                LDSM_X4(bl[j][0], bl[j][1], bl[j][2], bl[j][3], bL + o);
            }
#pragma unroll
            for (int i = 0; i < 4; i++) {
#pragma unroll
                for (int jn = 0; jn < 4; jn++) {
                    const int j = jn >> 1, s = jn & 1;
                    MMA_BF16(acc[i][jn], ah[i], bh[j][s], bh[j][s + 2]);   // Ah*Bh
                    MMA_BF16(acc[i][jn], ah[i], bl[j][s], bl[j][s + 2]);   // Ah*Bl
                    MMA_BF16(acc[i][jn], al[i], bh[j][s], bh[j][s + 2]);   // Al*Bh
                }
            }
        }
        __syncthreads();
        if (c + 2 < GK_CHUNKS) load_stage(c + 2, c & 1);
    }

    // epilogue: fragment (i,jn): rows m0+wm*64+i*16+(lane>>2){,+8},
    //           cols n0+wn*32+jn*8+(lane&3)*2
    const int er = lane >> 2;
    const int ec = (lane & 3) * 2;
#pragma unroll
    for (int i = 0; i < 4; i++) {
        int r0 = m0 + wm * 64 + i * 16 + er;
#pragma unroll
        for (int jn = 0; jn < 4; jn++) {
            int col = n0 + wn * 32 + jn * 8 + ec;
            *(float2*)(C + (size_t)r0 * N + col)       = make_float2(acc[i][jn][0], acc[i][jn][1]);
            *(float2*)(C + (size_t)(r0 + 8) * N + col) = make_float2(acc[i][jn][2], acc[i][jn][3]);
        }
    }
}

// ===========================================================================
// RoPE (validated)
// ===========================================================================
__global__ void rope_kernel(float* __restrict__ qkv, const int* __restrict__ pos_offset)
{
    int idx = blockIdx.x * blockDim.x + threadIdx.x;
    int d  = idx & 31;
    int h  = (idx >> 5) % N_HEADS_C;
    int w  = (idx / (32 * N_HEADS_C)) & 1;
    int bl = idx / (32 * N_HEADS_C * 2);
    int l  = bl & (L_SEQ - 1);

    float tpos = (float)(l + *pos_offset);
    float inv  = (float)exp2(-(double)d * (13.287712379549449 / 32.0));
    float fr   = tpos * inv;

    float n  = rintf(fr * 0.15915494309189535f);
    float r1 = fmaf(n, -6.2831855f, fr);
    float r  = fmaf(n,  1.7484556e-7f, r1);

    float s, c;
    __sincosf(r, &s, &c);

    float* base = qkv + (size_t)bl * QKV_COLS + w * D_MODEL + h * DH;
    float x1 = base[d];
    float x2 = base[d + 32];
    base[d]      = x1 * c - x2 * s;
    base[d + 32] = x2 * c + x1 * s;
}

// ===========================================================================
// Flash attention (fp32, validated)
// ===========================================================================
#define ATT_BM 128
#define ATT_BN 64
#define ATT_SMEM ((ATT_BN * DH + ATT_BN * DH + ATT_BN * ATT_BM) * 4)

__global__ __launch_bounds__(128) void attn_kernel(
    const float* __restrict__ qkv, float* __restrict__ outp)
{
    float* smem = (float*)dyn_smem;
    float (*kbuf)[DH]     = (float(*)[DH])smem;
    float (*vbuf)[DH]     = (float(*)[DH])(smem + ATT_BN * DH);
    float (*sbuf)[ATT_BM] = (float(*)[ATT_BM])(smem + 2 * ATT_BN * DH);

    const int qt = blockIdx.x;
    const int bh = blockIdx.y;
    const int b  = bh / N_HEADS_C;
    const int h  = bh % N_HEADS_C;
    const int r  = threadIdx.x;

    const float* qbase = qkv + (size_t)b * L_SEQ * QKV_COLS + h * DH;
    const float* kbase = qbase + D_MODEL;
    const float* vbase = qbase + 2 * D_MODEL;

    float q[DH];
#pragma unroll
    for (int c = 0; c < 2; c++) {
        const float* gsrc = qbase + (size_t)(qt * ATT_BM + c * 64) * QKV_COLS;
#pragma unroll
        for (int i = 0; i < 8; i++) {
            int idx = i * 128 + r;
            int row = idx >> 4;
            int c4  = (idx & 15) << 2;
            *(float4*)&kbuf[row][c4] = *(const float4*)(gsrc + (size_t)row * QKV_COLS + c4);
        }
        __syncthreads();
        if ((r >> 6) == c) {
            int rr = r & 63;
#pragma unroll
            for (int d = 0; d < DH; d++) q[d] = kbuf[rr][d] * 0.125f;
        }
        __syncthreads();
    }

    float m = -INFINITY, lsum = 0.f;
    float o[DH];
#pragma unroll
    for (int d = 0; d < DH; d++) o[d] = 0.f;

    const int qrow = qt * ATT_BM + r;
    const int ktmax = 2 * qt + 1;

    for (int kt = 0; kt <= ktmax; kt++) {
        const float* kg = kbase + (size_t)(kt * ATT_BN) * QKV_COLS;
        const float* vg = vbase + (size_t)(kt * ATT_BN) * QKV_COLS;
#pragma unroll
        for (int i = 0; i < 8; i++) {
            int idx = i * 128 + r;
            int row = idx >> 4;
            int c4  = (idx & 15) << 2;
            *(float4*)&kbuf[row][c4] = *(const float4*)(kg + (size_t)row * QKV_COLS + c4);
            *(float4*)&vbuf[row][c4] = *(const float4*)(vg + (size_t)row * QKV_COLS + c4);
        }
        __syncthreads();

        const int jlim = qrow - kt * ATT_BN;
        float smax = -INFINITY;

        for (int j = 0; j < ATT_BN; j++) {
            const float4* kr = (const float4*)kbuf[j];
            float s0 = 0.f, s1 = 0.f, s2 = 0.f, s3 = 0.f;
#pragma unroll
            for (int d4 = 0; d4 < 16; d4 += 4) {
                float4 kv0 = kr[d4 + 0];
                s0 += q[4*d4 + 0]*kv0.x + q[4*d4 + 1]*kv0.y + q[4*d4 + 2]*kv0.z + q[4*d4 + 3]*kv0.w;
                float4 kv1 = kr[d4 + 1];
                s1 += q[4*d4 + 4]*kv1.x + q[4*d4 + 5]*kv1.y + q[4*d4 + 6]*kv1.z + q[4*d4 + 7]*kv1.w;
                float4 kv2 = kr[d4 + 2];
                s2 += q[4*d4 + 8]*kv2.x + q[4*d4 + 9]*kv2.y + q[4*d4 +10]*kv2.z + q[4*d4 +11]*kv2.w;
                float4 kv3 = kr[d4 + 3];
                s3 += q[4*d4 +12]*kv3.x + q[4*d4 +13]*kv3.y + q[4*d4 +14]*kv3.z + q[4*d4 +15]*kv3.w;
            }
            float s = (s0 + s1) + (s2 + s3);
            s = (j <= jlim) ? s : -INFINITY;
            sbuf[j][r] = s;
            smax = fmaxf(smax, s);
        }

        float mnew = fmaxf(m, smax);
        float corr = __expf(m - mnew);
        lsum *= corr;
#pragma unroll
        for (int d = 0; d < DH; d++) o[d] *= corr;

        for (int j = 0; j < ATT_BN; j++) {
            float p = __expf(sbuf[j][r] - mnew);
            lsum += p;
            const float4* vr = (const float4*)vbuf[j];
#pragma unroll
            for (int d4 = 0; d4 < 16; d4++) {
                float4 vv = vr[d4];
                o[4*d4 + 0] += p * vv.x;
                o[4*d4 + 1] += p * vv.y;
                o[4*d4 + 2] += p * vv.z;
                o[4*d4 + 3] += p * vv.w;
            }
        }
        m = mnew;
        __syncthreads();
    }

    float inv = 1.f / lsum;
    float* op = outp + (size_t)(b * L_SEQ + qrow) * D_MODEL + h * DH;
#pragma unroll
    for (int d4 = 0; d4 < 16; d4++) {
        *(float4*)(op + 4 * d4) = make_float4(o[4*d4 + 0] * inv, o[4*d4 + 1] * inv,
                                              o[4*d4 + 2] * inv, o[4*d4 + 3] * inv);
    }
}

// ===========================================================================
// launch
// ===========================================================================
extern "C" void kernel_launch(void* const* d_in, const int* in_sizes, int n_in,
                              void* d_out, int out_size)
{
    const float* x     = (const float*)d_in[0];
    const float* w_qkv = (const float*)d_in[1];
    const float* w_out = (const float*)d_in[2];
    const int*   pos   = (const int*)d_in[3];
    float*       out   = (float*)d_out;

    float *qkvp = nullptr, *attp = nullptr;
    __nv_bfloat16 *xh, *xl, *wqh, *wql, *ah, *al, *woh, *wol;
    cudaGetSymbolAddress((void**)&qkvp, g_qkv);
    cudaGetSymbolAddress((void**)&attp, g_att);
    cudaGetSymbolAddress((void**)&xh, g_xh);   cudaGetSymbolAddress((void**)&xl, g_xl);
    cudaGetSymbolAddress((void**)&wqh, g_wqh); cudaGetSymbolAddress((void**)&wql, g_wql);
    cudaGetSymbolAddress((void**)&ah, g_ah);   cudaGetSymbolAddress((void**)&al, g_al);
    cudaGetSymbolAddress((void**)&woh, g_woh); cudaGetSymbolAddress((void**)&wol, g_wol);

    cudaFuncSetAttribute(attn_kernel, cudaFuncAttributeMaxDynamicSharedMemorySize, ATT_SMEM);
    cudaFuncSetAttribute(gemm_bf16x3, cudaFuncAttributeMaxDynamicSharedMemorySize, GEMM_SMEM);

    // 1) split inputs to bf16 hi/lo
    split_bf16<<<(M_ROWS * K_DIM / 4 + 255) / 256, 256>>>(x, xh, xl, M_ROWS * K_DIM / 4);
    split_bf16<<<(QKV_COLS * K_DIM / 4 + 255) / 256, 256>>>(w_qkv, wqh, wql, QKV_COLS * K_DIM / 4);

    // 2) QKV projection (tensor cores via mma.sync)
    gemm_bf16x3<<<dim3(QKV_COLS / 128, M_ROWS / 128), 256, GEMM_SMEM>>>(
        xh, xl, wqh, wql, qkvp, QKV_COLS);

    // 3) RoPE in place
    int rope_total = M_ROWS * 2 * N_HEADS_C * 32;
    rope_kernel<<<rope_total / 256, 256>>>(qkvp, pos);

    // 4) causal flash attention (fp32)
    attn_kernel<<<dim3(L_SEQ / ATT_BM, B_SZ * N_HEADS_C), 128, ATT_SMEM>>>(qkvp, attp);

    // 5) output projection (tensor cores via mma.sync)
    split_bf16<<<(M_ROWS * K_DIM / 4 + 255) / 256, 256>>>(attp, ah, al, M_ROWS * K_DIM / 4);
    split_bf16<<<(D_MODEL * K_DIM / 4 + 255) / 256, 256>>>(w_out, woh, wol, D_MODEL * K_DIM / 4);
    gemm_bf16x3<<<dim3(D_MODEL / 128, M_ROWS / 128), 256, GEMM_SMEM>>>(
        ah, al, woh, wol, out, D_MODEL);
}

// round 6
// speedup vs baseline: 4.7895x; 1.8643x over previous
#include <cuda_runtime.h>
#include <cuda_bf16.h>
#include <math.h>
#include <stdint.h>

// ---------------- problem constants ----------------
#define D_MODEL   1536
#define N_HEADS_C 24
#define DH        64
#define B_SZ      4
#define L_SEQ     2048
#define M_ROWS    (B_SZ * L_SEQ)     // 8192
#define QKV_COLS  (3 * D_MODEL)      // 4608
#define K_DIM     1536

// single dynamic smem symbol shared by all kernels
extern __shared__ char dyn_smem[];

// ---------------- scratch (device globals; no allocation allowed) ---------
__device__ float g_qkv[(size_t)M_ROWS * QKV_COLS];
__device__ float g_att[(size_t)M_ROWS * D_MODEL];
__device__ __nv_bfloat16 g_qkvh[(size_t)M_ROWS * QKV_COLS];
__device__ __nv_bfloat16 g_qkvl[(size_t)M_ROWS * QKV_COLS];
__device__ __nv_bfloat16 g_xh[(size_t)M_ROWS * K_DIM];
__device__ __nv_bfloat16 g_xl[(size_t)M_ROWS * K_DIM];
__device__ __nv_bfloat16 g_wqh[(size_t)QKV_COLS * K_DIM];
__device__ __nv_bfloat16 g_wql[(size_t)QKV_COLS * K_DIM];
__device__ __nv_bfloat16 g_ah[(size_t)M_ROWS * K_DIM];
__device__ __nv_bfloat16 g_al[(size_t)M_ROWS * K_DIM];
__device__ __nv_bfloat16 g_woh[(size_t)D_MODEL * K_DIM];
__device__ __nv_bfloat16 g_wol[(size_t)D_MODEL * K_DIM];

// inv_freq[d] = 10000^(-d/32) = 10^(-d/8), double-accurate, rounded to fp32
__constant__ float c_invf[32] = {
    1.0f, 0.7498942093324559f, 0.5623413251903491f, 0.42169650342858224f,
    0.31622776601683794f, 0.23713737056616552f, 0.1778279410038923f, 0.1333521432163324f,
    0.1f, 0.07498942093324558f, 0.05623413251903491f, 0.042169650342858224f,
    0.031622776601683794f, 0.023713737056616552f, 0.01778279410038923f, 0.01333521432163324f,
    0.01f, 0.007498942093324558f, 0.005623413251903491f, 0.0042169650342858224f,
    0.0031622776601683794f, 0.0023713737056616552f, 0.001778279410038923f, 0.0013335214321633241f,
    0.001f, 0.0007498942093324558f, 0.0005623413251903491f, 0.00042169650342858224f,
    0.00031622776601683794f, 0.00023713737056616552f, 0.0001778279410038923f, 0.00013335214321633242f
};

// ---------------- helpers --------------------------------------------------
__device__ __forceinline__ uint32_t smem_u32(const void* p) {
    uint32_t a;
    asm("{ .reg .u64 t; cvta.to.shared.u64 t, %1; cvt.u32.u64 %0, t; }" : "=r"(a) : "l"(p));
    return a;
}

#define CP_ASYNC16(dst, src) \
    asm volatile("cp.async.cg.shared.global [%0], [%1], 16;" :: "r"(dst), "l"(src))
#define CP_COMMIT() asm volatile("cp.async.commit_group;" ::: "memory")
#define CP_WAIT(N)  asm volatile("cp.async.wait_group %0;" :: "n"(N) : "memory")

#define LDSM_X4(r0, r1, r2, r3, addr) \
    asm volatile("ldmatrix.sync.aligned.m8n8.x4.shared.b16 {%0,%1,%2,%3}, [%4];" \
        : "=r"(r0), "=r"(r1), "=r"(r2), "=r"(r3) : "r"(addr))

#define LDSM_X4_T(r0, r1, r2, r3, addr) \
    asm volatile("ldmatrix.sync.aligned.m8n8.x4.trans.shared.b16 {%0,%1,%2,%3}, [%4];" \
        : "=r"(r0), "=r"(r1), "=r"(r2), "=r"(r3) : "r"(addr))

#define MMA_BF16(c, a, b0_, b1_) \
    asm volatile("mma.sync.aligned.m16n8k16.row.col.f32.bf16.bf16.f32 " \
        "{%0,%1,%2,%3}, {%4,%5,%6,%7}, {%8,%9}, {%0,%1,%2,%3};" \
        : "+f"((c)[0]), "+f"((c)[1]), "+f"((c)[2]), "+f"((c)[3]) \
        : "r"((a)[0]), "r"((a)[1]), "r"((a)[2]), "r"((a)[3]), "r"(b0_), "r"(b1_))

__device__ __forceinline__ uint32_t sw128(uint32_t off) {
    return off ^ ((off >> 3) & 0x70);
}

__device__ __forceinline__ uint32_t pack_bf16(float lo, float hi) {
    uint32_t d;
    asm("cvt.rn.bf16x2.f32 %0, %1, %2;" : "=r"(d) : "f"(hi), "f"(lo));
    return d;
}

// ===========================================================================
// split fp32 -> bf16 hi + bf16 lo
// ===========================================================================
__global__ __launch_bounds__(256) void split_bf16(
    const float* __restrict__ s, __nv_bfloat16* __restrict__ hi,
    __nv_bfloat16* __restrict__ lo, int n4)
{
    int i = blockIdx.x * blockDim.x + threadIdx.x;
    if (i >= n4) return;
    float4 v = ((const float4*)s)[i];
    uint32_t h01 = pack_bf16(v.x, v.y);
    uint32_t h23 = pack_bf16(v.z, v.w);
    float f0 = __uint_as_float(h01 << 16), f1 = __uint_as_float(h01 & 0xFFFF0000u);
    float f2 = __uint_as_float(h23 << 16), f3 = __uint_as_float(h23 & 0xFFFF0000u);
    uint32_t l01 = pack_bf16(v.x - f0, v.y - f1);
    uint32_t l23 = pack_bf16(v.z - f2, v.w - f3);
    ((uint2*)hi)[i] = make_uint2(h01, h23);
    ((uint2*)lo)[i] = make_uint2(l01, l23);
}

// ===========================================================================
// Split-bf16 3-product GEMM via mma.sync (validated round 5)
// ===========================================================================
#define GK_CHUNKS 24
#define TILE_B    16384
#define STAGE_B   (4 * TILE_B)
#define GEMM_SMEM (2 * STAGE_B)

__global__ __launch_bounds__(256, 1) void gemm_bf16x3(
    const __nv_bfloat16* __restrict__ Ah, const __nv_bfloat16* __restrict__ Al,
    const __nv_bfloat16* __restrict__ Bh, const __nv_bfloat16* __restrict__ Bl,
    float* __restrict__ C, int N)
{
    const uint32_t sbu = smem_u32(dyn_smem);

    const int tid  = threadIdx.x;
    const int wid  = tid >> 5;
    const int lane = tid & 31;
    const int wm   = wid & 1;
    const int wn   = wid >> 1;
    const int m0   = blockIdx.y * 128;
    const int n0   = blockIdx.x * 128;

    const __nv_bfloat16* srcs[4] = {
        Ah + (size_t)m0 * K_DIM, Al + (size_t)m0 * K_DIM,
        Bh + (size_t)n0 * K_DIM, Bl + (size_t)n0 * K_DIM };

    int unit_row[4], unit_u[4];
#pragma unroll
    for (int i = 0; i < 4; i++) {
        int unit = tid + i * 256;
        unit_row[i] = unit >> 3;
        unit_u[i]   = unit & 7;
    }

    auto load_stage = [&](int c, int s) {
        uint32_t sb = sbu + s * STAGE_B;
#pragma unroll
        for (int op = 0; op < 4; op++) {
            const __nv_bfloat16* src = srcs[op] + c * 64;
            uint32_t ob = sb + op * TILE_B;
#pragma unroll
            for (int i = 0; i < 4; i++) {
                const __nv_bfloat16* g = src + (size_t)unit_row[i] * K_DIM + unit_u[i] * 8;
                uint32_t d = ob + sw128(unit_row[i] * 128 + unit_u[i] * 16);
                CP_ASYNC16(d, g);
            }
        }
        CP_COMMIT();
    };

    float acc[4][4][4];
#pragma unroll
    for (int i = 0; i < 4; i++)
#pragma unroll
        for (int j = 0; j < 4; j++)
#pragma unroll
            for (int k = 0; k < 4; k++) acc[i][j][k] = 0.f;

    load_stage(0, 0);
    load_stage(1, 1);

    const int lrow = lane & 15;
    const int lhalf = (lane >> 4) * 16;

    for (int c = 0; c < GK_CHUNKS; c++) {
        if (c + 2 < GK_CHUNKS) { CP_WAIT(1); } else { CP_WAIT(0); }
        __syncthreads();

        const uint32_t sb = sbu + (c & 1) * STAGE_B;
        const uint32_t aH = sb + 0 * TILE_B;
        const uint32_t aL = sb + 1 * TILE_B;
        const uint32_t bH = sb + 2 * TILE_B;
        const uint32_t bL = sb + 3 * TILE_B;

#pragma unroll
        for (int k16 = 0; k16 < 4; k16++) {
            const uint32_t kb = k16 * 32 + lhalf;
            uint32_t ah[4][4], al[4][4];
#pragma unroll
            for (int i = 0; i < 4; i++) {
                int row = wm * 64 + i * 16 + lrow;
                uint32_t o = sw128(row * 128 + kb);
                LDSM_X4(ah[i][0], ah[i][1], ah[i][2], ah[i][3], aH + o);
                LDSM_X4(al[i][0], al[i][1], al[i][2], al[i][3], aL + o);
            }
            uint32_t bh[2][4], bl[2][4];
#pragma unroll
            for (int j = 0; j < 2; j++) {
                int row = wn * 32 + j * 16 + lrow;
                uint32_t o = sw128(row * 128 + kb);
                LDSM_X4(bh[j][0], bh[j][1], bh[j][2], bh[j][3], bH + o);
                LDSM_X4(bl[j][0], bl[j][1], bl[j][2], bl[j][3], bL + o);
            }
#pragma unroll
            for (int i = 0; i < 4; i++) {
#pragma unroll
                for (int jn = 0; jn < 4; jn++) {
                    const int j = jn >> 1, s = jn & 1;
                    MMA_BF16(acc[i][jn], ah[i], bh[j][s], bh[j][s + 2]);
                    MMA_BF16(acc[i][jn], ah[i], bl[j][s], bl[j][s + 2]);
                    MMA_BF16(acc[i][jn], al[i], bh[j][s], bh[j][s + 2]);
                }
            }
        }
        __syncthreads();
        if (c + 2 < GK_CHUNKS) load_stage(c + 2, c & 1);
    }

    const int er = lane >> 2;
    const int ec = (lane & 3) * 2;
#pragma unroll
    for (int i = 0; i < 4; i++) {
        int r0 = m0 + wm * 64 + i * 16 + er;
#pragma unroll
        for (int jn = 0; jn < 4; jn++) {
            int col = n0 + wn * 32 + jn * 8 + ec;
            *(float2*)(C + (size_t)r0 * N + col)       = make_float2(acc[i][jn][0], acc[i][jn][1]);
            *(float2*)(C + (size_t)(r0 + 8) * N + col) = make_float2(acc[i][jn][2], acc[i][jn][3]);
        }
    }
}

// ===========================================================================
// RoPE with constant inv_freq table (no fp64)
// ===========================================================================
__global__ void rope_kernel(float* __restrict__ qkv, const int* __restrict__ pos_offset)
{
    int idx = blockIdx.x * blockDim.x + threadIdx.x;
    int d  = idx & 31;
    int h  = (idx >> 5) % N_HEADS_C;
    int w  = (idx / (32 * N_HEADS_C)) & 1;
    int bl = idx / (32 * N_HEADS_C * 2);
    int l  = bl & (L_SEQ - 1);

    float tpos = (float)(l + *pos_offset);
    float fr   = tpos * c_invf[d];

    float n  = rintf(fr * 0.15915494309189535f);
    float r1 = fmaf(n, -6.2831855f, fr);
    float r  = fmaf(n,  1.7484556e-7f, r1);

    float s, c;
    __sincosf(r, &s, &c);

    float* base = qkv + (size_t)bl * QKV_COLS + w * D_MODEL + h * DH;
    float x1 = base[d];
    float x2 = base[d + 32];
    base[d]      = x1 * c - x2 * s;
    base[d + 32] = x2 * c + x1 * s;
}

// ===========================================================================
// Tensor-core causal flash attention (split-bf16 3-product for both GEMMs)
// BM=128 (8 warps x m16), BN=64 keys/tile, double-buffered K/V hi/lo stages.
// ===========================================================================
#define FQH 0
#define FQL 16384
#define FST 32768          // stage region start
#define FSTG 32768         // bytes per stage: Kh,Kl,Vh,Vl (8KB each)
#define FA_SMEM (FST + 2 * FSTG)   // 98304

__global__ __launch_bounds__(256, 1) void attn_mma(
    const __nv_bfloat16* __restrict__ qkvh,
    const __nv_bfloat16* __restrict__ qkvl,
    float* __restrict__ outp)
{
    const uint32_t sbu = smem_u32(dyn_smem);
    const int tid  = threadIdx.x;
    const int wid  = tid >> 5;
    const int lane = tid & 31;
    const int lrow = lane & 15;
    const int lhalf = (lane >> 4) * 16;

    const int qt = gridDim.x - 1 - blockIdx.x;     // heavy CTAs first
    const int bh = blockIdx.y;
    const int b  = bh / N_HEADS_C;
    const int h  = bh % N_HEADS_C;
    const size_t rowbase = (size_t)b * L_SEQ;

    // ---- queue Q tiles (hi, lo) ----
    {
        int op  = tid >> 7;                        // 0: hi, 1: lo
        int row = tid & 127;
        const __nv_bfloat16* src = (op ? qkvl : qkvh)
            + (rowbase + qt * 128 + row) * QKV_COLS + h * DH;
        uint32_t dstb = sbu + (op ? FQL : FQH);
#pragma unroll
        for (int c = 0; c < 8; c++)
            CP_ASYNC16(dstb + sw128(row * 128 + c * 16), src + c * 8);
        CP_COMMIT();
    }

    const int ktmax = 2 * qt + 1;

    auto load_kv = [&](int kt, int s) {
        int op  = tid >> 6;                        // 0:Kh 1:Kl 2:Vh 3:Vl
        int row = tid & 63;
        const __nv_bfloat16* base = (op & 1) ? qkvl : qkvh;
        int colofs = (op >> 1) ? (2 * D_MODEL + h * DH) : (D_MODEL + h * DH);
        const __nv_bfloat16* src = base + (rowbase + kt * 64 + row) * QKV_COLS + colofs;
        uint32_t dstb = sbu + FST + s * FSTG + op * 8192;
#pragma unroll
        for (int c = 0; c < 8; c++)
            CP_ASYNC16(dstb + sw128(row * 128 + c * 16), src + c * 8);
        CP_COMMIT();
    };

    load_kv(0, 0);
    load_kv(1, 1);

    // ---- Q fragments into registers (held across all KV tiles) ----
    CP_WAIT(2);
    __syncthreads();
    uint32_t qh[4][4], ql[4][4];
#pragma unroll
    for (int c = 0; c < 4; c++) {
        uint32_t o = sw128((wid * 16 + lrow) * 128 + c * 32 + lhalf);
        LDSM_X4(qh[c][0], qh[c][1], qh[c][2], qh[c][3], sbu + FQH + o);
        LDSM_X4(ql[c][0], ql[c][1], ql[c][2], ql[c][3], sbu + FQL + o);
    }

    float oa[8][4];
#pragma unroll
    for (int nt = 0; nt < 8; nt++)
#pragma unroll
        for (int r = 0; r < 4; r++) oa[nt][r] = 0.f;
    float m0 = -INFINITY, m1 = -INFINITY, l0 = 0.f, l1 = 0.f;

    const int row0 = qt * 128 + wid * 16 + (lane >> 2);   // this thread's rows
    const int row1 = row0 + 8;
    const int colq = 2 * (lane & 3);

    for (int kt = 0; kt <= ktmax; kt++) {
        if (kt + 2 <= ktmax) { CP_WAIT(1); } else { CP_WAIT(0); }
        __syncthreads();

        const uint32_t su = sbu + FST + (kt & 1) * FSTG;
        const uint32_t KH = su, KL = su + 8192, VH = su + 16384, VL = su + 24576;

        // ---- scores: S = (Qh+Ql)(Kh+Kl)^T, drop Ql*Kl ----
        float sc[8][4];
#pragma unroll
        for (int nt = 0; nt < 8; nt++)
#pragma unroll
            for (int r = 0; r < 4; r++) sc[nt][r] = 0.f;

#pragma unroll
        for (int c = 0; c < 4; c++) {
            const uint32_t kb = c * 32 + lhalf;
#pragma unroll
            for (int g = 0; g < 4; g++) {
                uint32_t o = sw128((g * 16 + lrow) * 128 + kb);
                uint32_t kh4[4], kl4[4];
                LDSM_X4(kh4[0], kh4[1], kh4[2], kh4[3], KH + o);
                LDSM_X4(kl4[0], kl4[1], kl4[2], kl4[3], KL + o);
                MMA_BF16(sc[2 * g],     qh[c], kh4[0], kh4[2]);
                MMA_BF16(sc[2 * g + 1], qh[c], kh4[1], kh4[3]);
                MMA_BF16(sc[2 * g],     qh[c], kl4[0], kl4[2]);
                MMA_BF16(sc[2 * g + 1], qh[c], kl4[1], kl4[3]);
                MMA_BF16(sc[2 * g],     ql[c], kh4[0], kh4[2]);
                MMA_BF16(sc[2 * g + 1], ql[c], kh4[1], kh4[3]);
            }
        }

        // scale + causal mask (diagonal tiles only)
        const bool diag = (kt >= 2 * qt);
#pragma unroll
        for (int nt = 0; nt < 8; nt++) {
            int colg = kt * 64 + nt * 8 + colq;
#pragma unroll
            for (int r = 0; r < 4; r++) {
                float s = sc[nt][r] * 0.125f;
                if (diag) {
                    int cg = colg + (r & 1);
                    int rg = (r < 2) ? row0 : row1;
                    if (cg > rg) s = -1e30f;
                }
                sc[nt][r] = s;
            }
        }

        // row max (across 4 lanes of the quad)
        float rm0 = -INFINITY, rm1 = -INFINITY;
#pragma unroll
        for (int nt = 0; nt < 8; nt++) {
            rm0 = fmaxf(rm0, fmaxf(sc[nt][0], sc[nt][1]));
            rm1 = fmaxf(rm1, fmaxf(sc[nt][2], sc[nt][3]));
        }
        rm0 = fmaxf(rm0, __shfl_xor_sync(0xffffffffu, rm0, 1));
        rm0 = fmaxf(rm0, __shfl_xor_sync(0xffffffffu, rm0, 2));
        rm1 = fmaxf(rm1, __shfl_xor_sync(0xffffffffu, rm1, 1));
        rm1 = fmaxf(rm1, __shfl_xor_sync(0xffffffffu, rm1, 2));

        float m0n = fmaxf(m0, rm0), m1n = fmaxf(m1, rm1);
        float cr0 = __expf(m0 - m0n), cr1 = __expf(m1 - m1n);
        l0 *= cr0; l1 *= cr1;
#pragma unroll
        for (int nt = 0; nt < 8; nt++) {
            oa[nt][0] *= cr0; oa[nt][1] *= cr0;
            oa[nt][2] *= cr1; oa[nt][3] *= cr1;
        }
        m0 = m0n; m1 = m1n;

        // p = exp(s - m), split to bf16 hi/lo, pack A-fragments
        uint32_t pha[8], phb[8], pla[8], plb[8];
#pragma unroll
        for (int nt = 0; nt < 8; nt++) {
            float p0 = __expf(sc[nt][0] - m0n);
            float p1 = __expf(sc[nt][1] - m0n);
            float p2 = __expf(sc[nt][2] - m1n);
            float p3 = __expf(sc[nt][3] - m1n);
            l0 += p0 + p1; l1 += p2 + p3;
            uint32_t h01 = pack_bf16(p0, p1);
            uint32_t h23 = pack_bf16(p2, p3);
            pha[nt] = h01; phb[nt] = h23;
            float f0 = __uint_as_float(h01 << 16), f1 = __uint_as_float(h01 & 0xFFFF0000u);
            float f2 = __uint_as_float(h23 << 16), f3 = __uint_as_float(h23 & 0xFFFF0000u);
            pla[nt] = pack_bf16(p0 - f0, p1 - f1);
            plb[nt] = pack_bf16(p2 - f2, p3 - f3);
        }

        // ---- O += (Ph+Pl)(Vh+Vl), drop Pl*Vl ----
#pragma unroll
        for (int kc = 0; kc < 4; kc++) {
            uint32_t pah[4] = { pha[2 * kc], phb[2 * kc], pha[2 * kc + 1], phb[2 * kc + 1] };
            uint32_t pal[4] = { pla[2 * kc], plb[2 * kc], pla[2 * kc + 1], plb[2 * kc + 1] };
#pragma unroll
            for (int dp = 0; dp < 4; dp++) {
                uint32_t o = sw128((kc * 16 + lrow) * 128 + dp * 32 + lhalf);
                uint32_t vh4[4], vl4[4];
                LDSM_X4_T(vh4[0], vh4[1], vh4[2], vh4[3], VH + o);
                LDSM_X4_T(vl4[0], vl4[1], vl4[2], vl4[3], VL + o);
                MMA_BF16(oa[2 * dp],     pah, vh4[0], vh4[1]);
                MMA_BF16(oa[2 * dp + 1], pah, vh4[2], vh4[3]);
                MMA_BF16(oa[2 * dp],     pah, vl4[0], vl4[1]);
                MMA_BF16(oa[2 * dp + 1], pah, vl4[2], vl4[3]);
                MMA_BF16(oa[2 * dp],     pal, vh4[0], vh4[1]);
                MMA_BF16(oa[2 * dp + 1], pal, vh4[2], vh4[3]);
            }
        }

        __syncthreads();
        if (kt + 2 <= ktmax) load_kv(kt + 2, kt & 1);
    }

    // ---- epilogue ----
    l0 += __shfl_xor_sync(0xffffffffu, l0, 1);
    l0 += __shfl_xor_sync(0xffffffffu, l0, 2);
    l1 += __shfl_xor_sync(0xffffffffu, l1, 1);
    l1 += __shfl_xor_sync(0xffffffffu, l1, 2);
    float i0 = 1.f / l0, i1 = 1.f / l1;

    float* o0 = outp + (rowbase + row0) * D_MODEL + h * DH;
    float* o1 = outp + (rowbase + row1) * D_MODEL + h * DH;
#pragma unroll
    for (int nt = 0; nt < 8; nt++) {
        int col = nt * 8 + colq;
        *(float2*)(o0 + col) = make_float2(oa[nt][0] * i0, oa[nt][1] * i0);
        *(float2*)(o1 + col) = make_float2(oa[nt][2] * i1, oa[nt][3] * i1);
    }
}

// ===========================================================================
// launch
// ===========================================================================
extern "C" void kernel_launch(void* const* d_in, const int* in_sizes, int n_in,
                              void* d_out, int out_size)
{
    const float* x     = (const float*)d_in[0];
    const float* w_qkv = (const float*)d_in[1];
    const float* w_out = (const float*)d_in[2];
    const int*   pos   = (const int*)d_in[3];
    float*       out   = (float*)d_out;

    float *qkvp = nullptr, *attp = nullptr;
    __nv_bfloat16 *qkvh, *qkvl, *xh, *xl, *wqh, *wql, *ah, *al, *woh, *wol;
    cudaGetSymbolAddress((void**)&qkvp, g_qkv);
    cudaGetSymbolAddress((void**)&attp, g_att);
    cudaGetSymbolAddress((void**)&qkvh, g_qkvh); cudaGetSymbolAddress((void**)&qkvl, g_qkvl);
    cudaGetSymbolAddress((void**)&xh, g_xh);   cudaGetSymbolAddress((void**)&xl, g_xl);
    cudaGetSymbolAddress((void**)&wqh, g_wqh); cudaGetSymbolAddress((void**)&wql, g_wql);
    cudaGetSymbolAddress((void**)&ah, g_ah);   cudaGetSymbolAddress((void**)&al, g_al);
    cudaGetSymbolAddress((void**)&woh, g_woh); cudaGetSymbolAddress((void**)&wol, g_wol);

    cudaFuncSetAttribute(gemm_bf16x3, cudaFuncAttributeMaxDynamicSharedMemorySize, GEMM_SMEM);
    cudaFuncSetAttribute(attn_mma, cudaFuncAttributeMaxDynamicSharedMemorySize, FA_SMEM);

    // 1) split inputs to bf16 hi/lo
    split_bf16<<<(M_ROWS * K_DIM / 4 + 255) / 256, 256>>>(x, xh, xl, M_ROWS * K_DIM / 4);
    split_bf16<<<(QKV_COLS * K_DIM / 4 + 255) / 256, 256>>>(w_qkv, wqh, wql, QKV_COLS * K_DIM / 4);

    // 2) QKV projection
    gemm_bf16x3<<<dim3(QKV_COLS / 128, M_ROWS / 128), 256, GEMM_SMEM>>>(
        xh, xl, wqh, wql, qkvp, QKV_COLS);

    // 3) RoPE in place
    int rope_total = M_ROWS * 2 * N_HEADS_C * 32;
    rope_kernel<<<rope_total / 256, 256>>>(qkvp, pos);

    // 4) split rope'd qkv to bf16 hi/lo
    split_bf16<<<(M_ROWS * QKV_COLS / 4 + 255) / 256, 256>>>(
        qkvp, qkvh, qkvl, M_ROWS * QKV_COLS / 4);

    // 5) tensor-core causal flash attention
    attn_mma<<<dim3(L_SEQ / 128, B_SZ * N_HEADS_C), 256, FA_SMEM>>>(qkvh, qkvl, attp);

    // 6) output projection
    split_bf16<<<(M_ROWS * K_DIM / 4 + 255) / 256, 256>>>(attp, ah, al, M_ROWS * K_DIM / 4);
    split_bf16<<<(D_MODEL * K_DIM / 4 + 255) / 256, 256>>>(w_out, woh, wol, D_MODEL * K_DIM / 4);
    gemm_bf16x3<<<dim3(D_MODEL / 128, M_ROWS / 128), 256, GEMM_SMEM>>>(
        ah, al, woh, wol, out, D_MODEL);
}

// round 7
// speedup vs baseline: 5.0788x; 1.0604x over previous
#include <cuda_runtime.h>
#include <cuda_bf16.h>
#include <math.h>
#include <stdint.h>

// ---------------- problem constants ----------------
#define D_MODEL   1536
#define N_HEADS_C 24
#define DH        64
#define B_SZ      4
#define L_SEQ     2048
#define M_ROWS    (B_SZ * L_SEQ)     // 8192
#define QKV_COLS  (3 * D_MODEL)      // 4608
#define K_DIM     1536

// single dynamic smem symbol shared by all kernels
extern __shared__ char dyn_smem[];

// ---------------- scratch (device globals; no allocation allowed) ---------
__device__ __nv_bfloat16 g_qkvh[(size_t)M_ROWS * QKV_COLS];
__device__ __nv_bfloat16 g_qkvl[(size_t)M_ROWS * QKV_COLS];
__device__ __nv_bfloat16 g_xh[(size_t)M_ROWS * K_DIM];
__device__ __nv_bfloat16 g_xl[(size_t)M_ROWS * K_DIM];
__device__ __nv_bfloat16 g_wqh[(size_t)QKV_COLS * K_DIM];
__device__ __nv_bfloat16 g_wql[(size_t)QKV_COLS * K_DIM];
__device__ __nv_bfloat16 g_ah[(size_t)M_ROWS * K_DIM];
__device__ __nv_bfloat16 g_al[(size_t)M_ROWS * K_DIM];
__device__ __nv_bfloat16 g_woh[(size_t)D_MODEL * K_DIM];
__device__ __nv_bfloat16 g_wol[(size_t)D_MODEL * K_DIM];

// inv_freq[d] = 10000^(-d/32) = 10^(-d/8), double-accurate, rounded to fp32
__constant__ float c_invf[32] = {
    1.0f, 0.7498942093324559f, 0.5623413251903491f, 0.42169650342858224f,
    0.31622776601683794f, 0.23713737056616552f, 0.1778279410038923f, 0.1333521432163324f,
    0.1f, 0.07498942093324558f, 0.05623413251903491f, 0.042169650342858224f,
    0.031622776601683794f, 0.023713737056616552f, 0.01778279410038923f, 0.01333521432163324f,
    0.01f, 0.007498942093324558f, 0.005623413251903491f, 0.0042169650342858224f,
    0.0031622776601683794f, 0.0023713737056616552f, 0.001778279410038923f, 0.0013335214321633241f,
    0.001f, 0.0007498942093324558f, 0.0005623413251903491f, 0.00042169650342858224f,
    0.00031622776601683794f, 0.00023713737056616552f, 0.0001778279410038923f, 0.00013335214321633242f
};

// ---------------- helpers --------------------------------------------------
__device__ __forceinline__ uint32_t smem_u32(const void* p) {
    uint32_t a;
    asm("{ .reg .u64 t; cvta.to.shared.u64 t, %1; cvt.u32.u64 %0, t; }" : "=r"(a) : "l"(p));
    return a;
}

#define CP_ASYNC16(dst, src) \
    asm volatile("cp.async.cg.shared.global [%0], [%1], 16;" :: "r"(dst), "l"(src))
#define CP_COMMIT() asm volatile("cp.async.commit_group;" ::: "memory")
#define CP_WAIT(N)  asm volatile("cp.async.wait_group %0;" :: "n"(N) : "memory")

#define LDSM_X4(r0, r1, r2, r3, addr) \
    asm volatile("ldmatrix.sync.aligned.m8n8.x4.shared.b16 {%0,%1,%2,%3}, [%4];" \
        : "=r"(r0), "=r"(r1), "=r"(r2), "=r"(r3) : "r"(addr))

#define LDSM_X4_T(r0, r1, r2, r3, addr) \
    asm volatile("ldmatrix.sync.aligned.m8n8.x4.trans.shared.b16 {%0,%1,%2,%3}, [%4];" \
        : "=r"(r0), "=r"(r1), "=r"(r2), "=r"(r3) : "r"(addr))

#define MMA_BF16(c, a, b0_, b1_) \
    asm volatile("mma.sync.aligned.m16n8k16.row.col.f32.bf16.bf16.f32 " \
        "{%0,%1,%2,%3}, {%4,%5,%6,%7}, {%8,%9}, {%0,%1,%2,%3};" \
        : "+f"((c)[0]), "+f"((c)[1]), "+f"((c)[2]), "+f"((c)[3]) \
        : "r"((a)[0]), "r"((a)[1]), "r"((a)[2]), "r"((a)[3]), "r"(b0_), "r"(b1_))

__device__ __forceinline__ uint32_t sw128(uint32_t off) {
    return off ^ ((off >> 3) & 0x70);
}

__device__ __forceinline__ uint32_t pack_bf16(float lo, float hi) {
    uint32_t d;
    asm("cvt.rn.bf16x2.f32 %0, %1, %2;" : "=r"(d) : "f"(hi), "f"(lo));
    return d;
}

__device__ __forceinline__ void sincos_rope(float fr, float* s, float* c) {
    float n  = rintf(fr * 0.15915494309189535f);
    float r1 = fmaf(n, -6.2831855f, fr);
    float r  = fmaf(n,  1.7484556e-7f, r1);
    __sincosf(r, s, c);
}

// ===========================================================================
// split fp32 -> bf16 hi + bf16 lo
// ===========================================================================
__global__ __launch_bounds__(256) void split_bf16(
    const float* __restrict__ s, __nv_bfloat16* __restrict__ hi,
    __nv_bfloat16* __restrict__ lo, int n4)
{
    int i = blockIdx.x * blockDim.x + threadIdx.x;
    if (i >= n4) return;
    float4 v = ((const float4*)s)[i];
    uint32_t h01 = pack_bf16(v.x, v.y);
    uint32_t h23 = pack_bf16(v.z, v.w);
    float f0 = __uint_as_float(h01 << 16), f1 = __uint_as_float(h01 & 0xFFFF0000u);
    float f2 = __uint_as_float(h23 << 16), f3 = __uint_as_float(h23 & 0xFFFF0000u);
    uint32_t l01 = pack_bf16(v.x - f0, v.y - f1);
    uint32_t l23 = pack_bf16(v.z - f2, v.w - f3);
    ((uint2*)hi)[i] = make_uint2(h01, h23);
    ((uint2*)lo)[i] = make_uint2(l01, l23);
}

// ===========================================================================
// Split-bf16 3-product GEMM via mma.sync.
// Epilogue modes: Chi==null -> fp32 store to C.
//                 Chi!=null -> write bf16 hi/lo; q/k column sections get RoPE
//                 (smem-staged), v section takes the direct register path.
// ===========================================================================
#define GK_CHUNKS 24
#define TILE_B    16384
#define STAGE_B   (4 * TILE_B)
#define GEMM_SMEM (2 * STAGE_B)

__global__ __launch_bounds__(256, 1) void gemm_bf16x3(
    const __nv_bfloat16* __restrict__ Ah, const __nv_bfloat16* __restrict__ Al,
    const __nv_bfloat16* __restrict__ Bh, const __nv_bfloat16* __restrict__ Bl,
    float* __restrict__ C,
    __nv_bfloat16* __restrict__ Chi, __nv_bfloat16* __restrict__ Clo,
    const int* __restrict__ pos, int N)
{
    const uint32_t sbu = smem_u32(dyn_smem);

    const int tid  = threadIdx.x;
    const int wid  = tid >> 5;
    const int lane = tid & 31;
    const int wm   = wid & 1;
    const int wn   = wid >> 1;
    const int m0   = blockIdx.y * 128;
    const int n0   = blockIdx.x * 128;

    const __nv_bfloat16* srcs[4] = {
        Ah + (size_t)m0 * K_DIM, Al + (size_t)m0 * K_DIM,
        Bh + (size_t)n0 * K_DIM, Bl + (size_t)n0 * K_DIM };

    int unit_row[4], unit_u[4];
#pragma unroll
    for (int i = 0; i < 4; i++) {
        int unit = tid + i * 256;
        unit_row[i] = unit >> 3;
        unit_u[i]   = unit & 7;
    }

    auto load_stage = [&](int c, int s) {
        uint32_t sb = sbu + s * STAGE_B;
#pragma unroll
        for (int op = 0; op < 4; op++) {
            const __nv_bfloat16* src = srcs[op] + c * 64;
            uint32_t ob = sb + op * TILE_B;
#pragma unroll
            for (int i = 0; i < 4; i++) {
                const __nv_bfloat16* g = src + (size_t)unit_row[i] * K_DIM + unit_u[i] * 8;
                uint32_t d = ob + sw128(unit_row[i] * 128 + unit_u[i] * 16);
                CP_ASYNC16(d, g);
            }
        }
        CP_COMMIT();
    };

    float acc[4][4][4];
#pragma unroll
    for (int i = 0; i < 4; i++)
#pragma unroll
        for (int j = 0; j < 4; j++)
#pragma unroll
            for (int k = 0; k < 4; k++) acc[i][j][k] = 0.f;

    load_stage(0, 0);
    load_stage(1, 1);

    const int lrow = lane & 15;
    const int lhalf = (lane >> 4) * 16;

    for (int c = 0; c < GK_CHUNKS; c++) {
        if (c + 2 < GK_CHUNKS) { CP_WAIT(1); } else { CP_WAIT(0); }
        __syncthreads();

        const uint32_t sb = sbu + (c & 1) * STAGE_B;
        const uint32_t aH = sb + 0 * TILE_B;
        const uint32_t aL = sb + 1 * TILE_B;
        const uint32_t bH = sb + 2 * TILE_B;
        const uint32_t bL = sb + 3 * TILE_B;

#pragma unroll
        for (int k16 = 0; k16 < 4; k16++) {
            const uint32_t kb = k16 * 32 + lhalf;
            uint32_t ah[4][4], al[4][4];
#pragma unroll
            for (int i = 0; i < 4; i++) {
                int row = wm * 64 + i * 16 + lrow;
                uint32_t o = sw128(row * 128 + kb);
                LDSM_X4(ah[i][0], ah[i][1], ah[i][2], ah[i][3], aH + o);
                LDSM_X4(al[i][0], al[i][1], al[i][2], al[i][3], aL + o);
            }
            uint32_t bh[2][4], bl[2][4];
#pragma unroll
            for (int j = 0; j < 2; j++) {
                int row = wn * 32 + j * 16 + lrow;
                uint32_t o = sw128(row * 128 + kb);
                LDSM_X4(bh[j][0], bh[j][1], bh[j][2], bh[j][3], bH + o);
                LDSM_X4(bl[j][0], bl[j][1], bl[j][2], bl[j][3], bL + o);
            }
#pragma unroll
            for (int i = 0; i < 4; i++) {
#pragma unroll
                for (int jn = 0; jn < 4; jn++) {
                    const int j = jn >> 1, s = jn & 1;
                    MMA_BF16(acc[i][jn], ah[i], bh[j][s], bh[j][s + 2]);
                    MMA_BF16(acc[i][jn], ah[i], bl[j][s], bl[j][s + 2]);
                    MMA_BF16(acc[i][jn], al[i], bh[j][s], bh[j][s + 2]);
                }
            }
        }
        __syncthreads();
        if (c + 2 < GK_CHUNKS) load_stage(c + 2, c & 1);
    }

    const int er = lane >> 2;
    const int ec = (lane & 3) * 2;

    if (!Chi) {
        // plain fp32 epilogue
#pragma unroll
        for (int i = 0; i < 4; i++) {
            int r0 = m0 + wm * 64 + i * 16 + er;
#pragma unroll
            for (int jn = 0; jn < 4; jn++) {
                int col = n0 + wn * 32 + jn * 8 + ec;
                *(float2*)(C + (size_t)r0 * N + col)       = make_float2(acc[i][jn][0], acc[i][jn][1]);
                *(float2*)(C + (size_t)(r0 + 8) * N + col) = make_float2(acc[i][jn][2], acc[i][jn][3]);
            }
        }
    } else if (n0 >= 2 * D_MODEL) {
        // v section: direct register split-store (no rope)
#pragma unroll
        for (int i = 0; i < 4; i++) {
#pragma unroll
            for (int jn = 0; jn < 4; jn++) {
                int col = n0 + wn * 32 + jn * 8 + ec;
#pragma unroll
                for (int half = 0; half < 2; half++) {
                    int r = m0 + wm * 64 + i * 16 + er + half * 8;
                    float a0 = acc[i][jn][2 * half], a1 = acc[i][jn][2 * half + 1];
                    uint32_t hh = pack_bf16(a0, a1);
                    float f0 = __uint_as_float(hh << 16), f1 = __uint_as_float(hh & 0xFFFF0000u);
                    uint32_t ll = pack_bf16(a0 - f0, a1 - f1);
                    size_t o = (size_t)r * N + col;
                    *(uint32_t*)(Chi + o) = hh;
                    *(uint32_t*)(Clo + o) = ll;
                }
            }
        }
    } else {
        // q/k section: stage tile in smem, apply RoPE, split-store
        float* Ct = (float*)dyn_smem;                    // [128][130]
#pragma unroll
        for (int i = 0; i < 4; i++) {
            int rl = wm * 64 + i * 16 + er;
#pragma unroll
            for (int jn = 0; jn < 4; jn++) {
                int cl = wn * 32 + jn * 8 + ec;
                Ct[rl * 130 + cl]           = acc[i][jn][0];
                Ct[rl * 130 + cl + 1]       = acc[i][jn][1];
                Ct[(rl + 8) * 130 + cl]     = acc[i][jn][2];
                Ct[(rl + 8) * 130 + cl + 1] = acc[i][jn][3];
            }
        }
        __syncthreads();
        const int po = *pos;
#pragma unroll
        for (int it = 0; it < 32; it++) {
            int idx = tid + it * 256;                    // 0..8191
            int hd  = idx & 63;                          // head*32 + d
            int row = idx >> 6;
            int d   = hd & 31;
            int cl  = (hd >> 5) * 64 + d;
            float x1 = Ct[row * 130 + cl];
            float x2 = Ct[row * 130 + cl + 32];
            int l = (m0 + row) & (L_SEQ - 1);
            float s, c;
            sincos_rope((float)(l + po) * c_invf[d], &s, &c);
            float y1 = x1 * c - x2 * s;
            float y2 = x2 * c + x1 * s;
            __nv_bfloat16 h1 = __float2bfloat16_rn(y1);
            __nv_bfloat16 h2 = __float2bfloat16_rn(y2);
            size_t o = (size_t)(m0 + row) * N + n0 + cl;
            Chi[o]      = h1;
            Chi[o + 32] = h2;
            Clo[o]      = __float2bfloat16_rn(y1 - __bfloat162float(h1));
            Clo[o + 32] = __float2bfloat16_rn(y2 - __bfloat162float(h2));
        }
    }
}

// ===========================================================================
// Tensor-core causal flash attention (split-bf16 3-product for both GEMMs).
// Writes bf16 hi/lo output directly (feeds the out-projection GEMM).
// ===========================================================================
#define FQH 0
#define FQL 16384
#define FST 32768
#define FSTG 32768
#define FA_SMEM (FST + 2 * FSTG)   // 98304

__global__ __launch_bounds__(256, 1) void attn_mma(
    const __nv_bfloat16* __restrict__ qkvh,
    const __nv_bfloat16* __restrict__ qkvl,
    __nv_bfloat16* __restrict__ ohp,
    __nv_bfloat16* __restrict__ olp)
{
    const uint32_t sbu = smem_u32(dyn_smem);
    const int tid  = threadIdx.x;
    const int wid  = tid >> 5;
    const int lane = tid & 31;
    const int lrow = lane & 15;
    const int lhalf = (lane >> 4) * 16;

    const int qt = gridDim.x - 1 - blockIdx.x;     // heavy CTAs first
    const int bh = blockIdx.y;
    const int b  = bh / N_HEADS_C;
    const int h  = bh % N_HEADS_C;
    const size_t rowbase = (size_t)b * L_SEQ;

    // ---- queue Q tiles (hi, lo) ----
    {
        int op  = tid >> 7;
        int row = tid & 127;
        const __nv_bfloat16* src = (op ? qkvl : qkvh)
            + (rowbase + qt * 128 + row) * QKV_COLS + h * DH;
        uint32_t dstb = sbu + (op ? FQL : FQH);
#pragma unroll
        for (int c = 0; c < 8; c++)
            CP_ASYNC16(dstb + sw128(row * 128 + c * 16), src + c * 8);
        CP_COMMIT();
    }

    const int ktmax = 2 * qt + 1;

    auto load_kv = [&](int kt, int s) {
        int op  = tid >> 6;                        // 0:Kh 1:Kl 2:Vh 3:Vl
        int row = tid & 63;
        const __nv_bfloat16* base = (op & 1) ? qkvl : qkvh;
        int colofs = (op >> 1) ? (2 * D_MODEL + h * DH) : (D_MODEL + h * DH);
        const __nv_bfloat16* src = base + (rowbase + kt * 64 + row) * QKV_COLS + colofs;
        uint32_t dstb = sbu + FST + s * FSTG + op * 8192;
#pragma unroll
        for (int c = 0; c < 8; c++)
            CP_ASYNC16(dstb + sw128(row * 128 + c * 16), src + c * 8);
        CP_COMMIT();
    };

    load_kv(0, 0);
    load_kv(1, 1);

    CP_WAIT(2);
    __syncthreads();
    uint32_t qh[4][4], ql[4][4];
#pragma unroll
    for (int c = 0; c < 4; c++) {
        uint32_t o = sw128((wid * 16 + lrow) * 128 + c * 32 + lhalf);
        LDSM_X4(qh[c][0], qh[c][1], qh[c][2], qh[c][3], sbu + FQH + o);
        LDSM_X4(ql[c][0], ql[c][1], ql[c][2], ql[c][3], sbu + FQL + o);
    }

    float oa[8][4];
#pragma unroll
    for (int nt = 0; nt < 8; nt++)
#pragma unroll
        for (int r = 0; r < 4; r++) oa[nt][r] = 0.f;
    float m0 = -INFINITY, m1 = -INFINITY, l0 = 0.f, l1 = 0.f;

    const int row0 = qt * 128 + wid * 16 + (lane >> 2);
    const int row1 = row0 + 8;
    const int colq = 2 * (lane & 3);

    for (int kt = 0; kt <= ktmax; kt++) {
        if (kt + 2 <= ktmax) { CP_WAIT(1); } else { CP_WAIT(0); }
        __syncthreads();

        const uint32_t su = sbu + FST + (kt & 1) * FSTG;
        const uint32_t KH = su, KL = su + 8192, VH = su + 16384, VL = su + 24576;

        float sc[8][4];
#pragma unroll
        for (int nt = 0; nt < 8; nt++)
#pragma unroll
            for (int r = 0; r < 4; r++) sc[nt][r] = 0.f;

#pragma unroll
        for (int c = 0; c < 4; c++) {
            const uint32_t kb = c * 32 + lhalf;
#pragma unroll
            for (int g = 0; g < 4; g++) {
                uint32_t o = sw128((g * 16 + lrow) * 128 + kb);
                uint32_t kh4[4], kl4[4];
                LDSM_X4(kh4[0], kh4[1], kh4[2], kh4[3], KH + o);
                LDSM_X4(kl4[0], kl4[1], kl4[2], kl4[3], KL + o);
                MMA_BF16(sc[2 * g],     qh[c], kh4[0], kh4[2]);
                MMA_BF16(sc[2 * g + 1], qh[c], kh4[1], kh4[3]);
                MMA_BF16(sc[2 * g],     qh[c], kl4[0], kl4[2]);
                MMA_BF16(sc[2 * g + 1], qh[c], kl4[1], kl4[3]);
                MMA_BF16(sc[2 * g],     ql[c], kh4[0], kh4[2]);
                MMA_BF16(sc[2 * g + 1], ql[c], kh4[1], kh4[3]);
            }
        }

        const bool diag = (kt >= 2 * qt);
#pragma unroll
        for (int nt = 0; nt < 8; nt++) {
            int colg = kt * 64 + nt * 8 + colq;
#pragma unroll
            for (int r = 0; r < 4; r++) {
                float s = sc[nt][r] * 0.125f;
                if (diag) {
                    int cg = colg + (r & 1);
                    int rg = (r < 2) ? row0 : row1;
                    if (cg > rg) s = -1e30f;
                }
                sc[nt][r] = s;
            }
        }

        float rm0 = -INFINITY, rm1 = -INFINITY;
#pragma unroll
        for (int nt = 0; nt < 8; nt++) {
            rm0 = fmaxf(rm0, fmaxf(sc[nt][0], sc[nt][1]));
            rm1 = fmaxf(rm1, fmaxf(sc[nt][2], sc[nt][3]));
        }
        rm0 = fmaxf(rm0, __shfl_xor_sync(0xffffffffu, rm0, 1));
        rm0 = fmaxf(rm0, __shfl_xor_sync(0xffffffffu, rm0, 2));
        rm1 = fmaxf(rm1, __shfl_xor_sync(0xffffffffu, rm1, 1));
        rm1 = fmaxf(rm1, __shfl_xor_sync(0xffffffffu, rm1, 2));

        float m0n = fmaxf(m0, rm0), m1n = fmaxf(m1, rm1);
        float cr0 = __expf(m0 - m0n), cr1 = __expf(m1 - m1n);
        l0 *= cr0; l1 *= cr1;
#pragma unroll
        for (int nt = 0; nt < 8; nt++) {
            oa[nt][0] *= cr0; oa[nt][1] *= cr0;
            oa[nt][2] *= cr1; oa[nt][3] *= cr1;
        }
        m0 = m0n; m1 = m1n;

        uint32_t pha[8], phb[8], pla[8], plb[8];
#pragma unroll
        for (int nt = 0; nt < 8; nt++) {
            float p0 = __expf(sc[nt][0] - m0n);
            float p1 = __expf(sc[nt][1] - m0n);
            float p2 = __expf(sc[nt][2] - m1n);
            float p3 = __expf(sc[nt][3] - m1n);
            l0 += p0 + p1; l1 += p2 + p3;
            uint32_t h01 = pack_bf16(p0, p1);
            uint32_t h23 = pack_bf16(p2, p3);
            pha[nt] = h01; phb[nt] = h23;
            float f0 = __uint_as_float(h01 << 16), f1 = __uint_as_float(h01 & 0xFFFF0000u);
            float f2 = __uint_as_float(h23 << 16), f3 = __uint_as_float(h23 & 0xFFFF0000u);
            pla[nt] = pack_bf16(p0 - f0, p1 - f1);
            plb[nt] = pack_bf16(p2 - f2, p3 - f3);
        }

#pragma unroll
        for (int kc = 0; kc < 4; kc++) {
            uint32_t pah[4] = { pha[2 * kc], phb[2 * kc], pha[2 * kc + 1], phb[2 * kc + 1] };
            uint32_t pal[4] = { pla[2 * kc], plb[2 * kc], pla[2 * kc + 1], plb[2 * kc + 1] };
#pragma unroll
            for (int dp = 0; dp < 4; dp++) {
                uint32_t o = sw128((kc * 16 + lrow) * 128 + dp * 32 + lhalf);
                uint32_t vh4[4], vl4[4];
                LDSM_X4_T(vh4[0], vh4[1], vh4[2], vh4[3], VH + o);
                LDSM_X4_T(vl4[0], vl4[1], vl4[2], vl4[3], VL + o);
                MMA_BF16(oa[2 * dp],     pah, vh4[0], vh4[1]);
                MMA_BF16(oa[2 * dp + 1], pah, vh4[2], vh4[3]);
                MMA_BF16(oa[2 * dp],     pah, vl4[0], vl4[1]);
                MMA_BF16(oa[2 * dp + 1], pah, vl4[2], vl4[3]);
                MMA_BF16(oa[2 * dp],     pal, vh4[0], vh4[1]);
                MMA_BF16(oa[2 * dp + 1], pal, vh4[2], vh4[3]);
            }
        }

        __syncthreads();
        if (kt + 2 <= ktmax) load_kv(kt + 2, kt & 1);
    }

    // ---- epilogue: normalize, split to bf16 hi/lo, store ----
    l0 += __shfl_xor_sync(0xffffffffu, l0, 1);
    l0 += __shfl_xor_sync(0xffffffffu, l0, 2);
    l1 += __shfl_xor_sync(0xffffffffu, l1, 1);
    l1 += __shfl_xor_sync(0xffffffffu, l1, 2);
    float i0 = 1.f / l0, i1 = 1.f / l1;

    size_t ob0 = (rowbase + row0) * D_MODEL + h * DH;
    size_t ob1 = (rowbase + row1) * D_MODEL + h * DH;
#pragma unroll
    for (int nt = 0; nt < 8; nt++) {
        int col = nt * 8 + colq;
        float a0 = oa[nt][0] * i0, a1 = oa[nt][1] * i0;
        float a2 = oa[nt][2] * i1, a3 = oa[nt][3] * i1;
        uint32_t h01 = pack_bf16(a0, a1);
        uint32_t h23 = pack_bf16(a2, a3);
        float f0 = __uint_as_float(h01 << 16), f1 = __uint_as_float(h01 & 0xFFFF0000u);
        float f2 = __uint_as_float(h23 << 16), f3 = __uint_as_float(h23 & 0xFFFF0000u);
        *(uint32_t*)(ohp + ob0 + col) = h01;
        *(uint32_t*)(olp + ob0 + col) = pack_bf16(a0 - f0, a1 - f1);
        *(uint32_t*)(ohp + ob1 + col) = h23;
        *(uint32_t*)(olp + ob1 + col) = pack_bf16(a2 - f2, a3 - f3);
    }
}

// ===========================================================================
// launch
// ===========================================================================
extern "C" void kernel_launch(void* const* d_in, const int* in_sizes, int n_in,
                              void* d_out, int out_size)
{
    const float* x     = (const float*)d_in[0];
    const float* w_qkv = (const float*)d_in[1];
    const float* w_out = (const float*)d_in[2];
    const int*   pos   = (const int*)d_in[3];
    float*       out   = (float*)d_out;

    __nv_bfloat16 *qkvh, *qkvl, *xh, *xl, *wqh, *wql, *ah, *al, *woh, *wol;
    cudaGetSymbolAddress((void**)&qkvh, g_qkvh); cudaGetSymbolAddress((void**)&qkvl, g_qkvl);
    cudaGetSymbolAddress((void**)&xh, g_xh);   cudaGetSymbolAddress((void**)&xl, g_xl);
    cudaGetSymbolAddress((void**)&wqh, g_wqh); cudaGetSymbolAddress((void**)&wql, g_wql);
    cudaGetSymbolAddress((void**)&ah, g_ah);   cudaGetSymbolAddress((void**)&al, g_al);
    cudaGetSymbolAddress((void**)&woh, g_woh); cudaGetSymbolAddress((void**)&wol, g_wol);

    cudaFuncSetAttribute(gemm_bf16x3, cudaFuncAttributeMaxDynamicSharedMemorySize, GEMM_SMEM);
    cudaFuncSetAttribute(attn_mma, cudaFuncAttributeMaxDynamicSharedMemorySize, FA_SMEM);

    // 1) split inputs to bf16 hi/lo
    split_bf16<<<(M_ROWS * K_DIM / 4 + 255) / 256, 256>>>(x, xh, xl, M_ROWS * K_DIM / 4);
    split_bf16<<<(QKV_COLS * K_DIM / 4 + 255) / 256, 256>>>(w_qkv, wqh, wql, QKV_COLS * K_DIM / 4);

    // 2) QKV projection with fused RoPE + hi/lo split epilogue
    gemm_bf16x3<<<dim3(QKV_COLS / 128, M_ROWS / 128), 256, GEMM_SMEM>>>(
        xh, xl, wqh, wql, nullptr, qkvh, qkvl, pos, QKV_COLS);

    // 3) tensor-core causal flash attention -> bf16 hi/lo
    attn_mma<<<dim3(L_SEQ / 128, B_SZ * N_HEADS_C), 256, FA_SMEM>>>(qkvh, qkvl, ah, al);

    // 4) output projection (plain fp32 epilogue to d_out)
    split_bf16<<<(D_MODEL * K_DIM / 4 + 255) / 256, 256>>>(w_out, woh, wol, D_MODEL * K_DIM / 4);
    gemm_bf16x3<<<dim3(D_MODEL / 128, M_ROWS / 128), 256, GEMM_SMEM>>>(
        ah, al, woh, wol, out, nullptr, nullptr, nullptr, D_MODEL);
}